// round 1
// baseline (speedup 1.0000x reference)
#include <cuda_runtime.h>

#define MROWS   512   // rows of weight / output dim
#define KDIM    20    // motion dim
#define OUT_DIM 512
#define BTILE   256   // batch rows per block in GEMM
#define GTHREADS 128  // 4 warps: 128 threads x 4 outputs = 512 outputs

// Q transposed: g_Qt[k*512 + o] = Q[o][k]
__device__ float g_Qt[KDIM * OUT_DIM];

// ---------------------------------------------------------------------------
// helpers
// ---------------------------------------------------------------------------
__device__ __forceinline__ float blockReduceSum(float x, float* red) {
    int lane = threadIdx.x & 31;
    int wid  = threadIdx.x >> 5;
    #pragma unroll
    for (int off = 16; off; off >>= 1) x += __shfl_xor_sync(0xffffffffu, x, off);
    if (lane == 0) red[wid] = x;
    __syncthreads();
    float s = (lane < 16) ? red[lane] : 0.f;   // 16 warps -> 16 partials
    #pragma unroll
    for (int off = 8; off; off >>= 1) s += __shfl_xor_sync(0xffffffffu, s, off);
    s = __shfl_sync(0xffffffffu, s, 0);
    __syncthreads();                            // protect red for next call
    return s;
}

__device__ __forceinline__ unsigned long long pack2(float lo, float hi) {
    unsigned long long r;
    asm("mov.b64 %0, {%1, %2};" : "=l"(r) : "f"(lo), "f"(hi));
    return r;
}

__device__ __forceinline__ unsigned long long ffma2(unsigned long long a,
                                                    unsigned long long b,
                                                    unsigned long long c) {
    unsigned long long d;
    asm("fma.rn.f32x2 %0, %1, %2, %3;" : "=l"(d) : "l"(a), "l"(b), "l"(c));
    return d;
}

// ---------------------------------------------------------------------------
// Householder QR (LAPACK sgeqr2 + sorg2r conventions) of W + 1e-8, W: [512,20]
// Single block, 512 threads (one per row). Writes Q^T to g_Qt.
// ---------------------------------------------------------------------------
__global__ void qr_kernel(const float* __restrict__ W) {
    __shared__ float sA[KDIM][MROWS];   // column-major: sA[c][t] = A[t][c]
    __shared__ float sV[MROWS];
    __shared__ float sTau[KDIM];
    __shared__ float sRed[16];

    const int t    = threadIdx.x;
    const int lane = t & 31;
    const int wid  = t >> 5;

    #pragma unroll
    for (int c = 0; c < KDIM; ++c)
        sA[c][t] = W[t * KDIM + c] + 1e-8f;
    __syncthreads();

    // ---- factorization (geqr2) ----
    for (int j = 0; j < KDIM; ++j) {
        float a  = sA[j][t];
        float sq = (t > j) ? a * a : 0.f;
        float xnorm2 = blockReduceSum(sq, sRed);
        float alpha  = sA[j][j];
        float beta   = -copysignf(sqrtf(alpha * alpha + xnorm2), alpha); // LAPACK sign
        float tau    = (beta - alpha) / beta;
        float inv    = 1.f / (alpha - beta);
        float v      = (t == j) ? 1.f : ((t > j) ? a * inv : 0.f);
        sV[t] = v;
        if (t == j)      { sTau[j] = tau; sA[j][j] = beta; }
        else if (t > j)  { sA[j][t] = v; }   // store reflector
        __syncthreads();

        // trailing update: one warp per column
        for (int c = j + 1 + wid; c < KDIM; c += 16) {
            float w = 0.f;
            #pragma unroll
            for (int i = lane; i < MROWS; i += 32) w += sV[i] * sA[c][i];
            #pragma unroll
            for (int off = 16; off; off >>= 1) w += __shfl_xor_sync(0xffffffffu, w, off);
            float tw = sTau[j] * w;
            #pragma unroll
            for (int i = lane; i < MROWS; i += 32) sA[c][i] -= tw * sV[i];
        }
        __syncthreads();
    }

    // ---- form Q in place (org2r) ----
    for (int j = KDIM - 1; j >= 0; --j) {
        float tau = sTau[j];
        float vt  = (t == j) ? 1.f : ((t > j) ? sA[j][t] : 0.f);
        sV[t] = vt;
        __syncthreads();

        for (int c = j + 1 + wid; c < KDIM; c += 16) {
            float w = 0.f;
            #pragma unroll
            for (int i = lane; i < MROWS; i += 32) w += sV[i] * sA[c][i];
            #pragma unroll
            for (int off = 16; off; off >>= 1) w += __shfl_xor_sync(0xffffffffu, w, off);
            float tw = tau * w;
            #pragma unroll
            for (int i = lane; i < MROWS; i += 32) sA[c][i] -= tw * sV[i];
        }
        __syncthreads();
        sA[j][t] = (t == j) ? (1.f - tau) : ((t > j) ? -tau * vt : 0.f);
        __syncthreads();
    }

    // store Q^T (coalesced per column)
    #pragma unroll
    for (int k = 0; k < KDIM; ++k)
        g_Qt[k * OUT_DIM + t] = sA[k][t];
}

// ---------------------------------------------------------------------------
// out[b][o] = sum_k input[b][k] * Q[o][k]
// Q fully register-resident (per-thread: 4 output cols x 20 k = 40 f32x2 pairs).
// Input staged in smem as duplicated pairs (x,x,y,y) so each LDS.128 gives two
// ready f32x2 broadcast operands (no packing MOVs in the hot loop).
// ---------------------------------------------------------------------------
__global__ void __launch_bounds__(GTHREADS)
gemm_kernel(const float* __restrict__ input, float* __restrict__ out, int batch) {
    __shared__ float4 sIn[BTILE * KDIM / 2];   // 2560 float4 = 40 KB

    const int tid = threadIdx.x;
    const long long b0 = (long long)blockIdx.x * BTILE;
    int rows = (batch - b0 < BTILE) ? (int)(batch - b0) : BTILE;

    // load this thread's Q columns (o = 4*tid .. 4*tid+3) into registers
    unsigned long long qa[KDIM], qb[KDIM];
    #pragma unroll
    for (int k = 0; k < KDIM; ++k) {
        float4 q = reinterpret_cast<const float4*>(g_Qt + k * OUT_DIM)[tid];
        qa[k] = pack2(q.x, q.y);
        qb[k] = pack2(q.z, q.w);
    }

    // stage input tile, duplicating each scalar into a pair
    const float4* inBlk = reinterpret_cast<const float4*>(input + b0 * KDIM);
    const int n4 = rows * KDIM / 4;            // rows*5 float4s
    for (int i = tid; i < n4; i += GTHREADS) {
        float4 v = inBlk[i];
        sIn[2 * i]     = make_float4(v.x, v.x, v.y, v.y);
        sIn[2 * i + 1] = make_float4(v.z, v.z, v.w, v.w);
    }
    __syncthreads();

    const ulonglong2* sIn2 = reinterpret_cast<const ulonglong2*>(sIn);
    float4* outp = reinterpret_cast<float4*>(out + b0 * OUT_DIM) + tid;

    #pragma unroll 2
    for (int r = 0; r < rows; ++r) {
        const ulonglong2* row = sIn2 + r * (KDIM / 2);
        unsigned long long acc0 = 0ull, acc1 = 0ull;   // (0.f, 0.f)
        #pragma unroll
        for (int p = 0; p < KDIM / 2; ++p) {
            ulonglong2 x = row[p];                     // (x2p,x2p),(x2p+1,x2p+1)
            acc0 = ffma2(x.x, qa[2 * p],     acc0);
            acc1 = ffma2(x.x, qb[2 * p],     acc1);
            acc0 = ffma2(x.y, qa[2 * p + 1], acc0);
            acc1 = ffma2(x.y, qb[2 * p + 1], acc1);
        }
        float4 res;
        res.x = __uint_as_float((unsigned)(acc0 & 0xffffffffull));
        res.y = __uint_as_float((unsigned)(acc0 >> 32));
        res.z = __uint_as_float((unsigned)(acc1 & 0xffffffffull));
        res.w = __uint_as_float((unsigned)(acc1 >> 32));
        outp[(long long)r * (OUT_DIM / 4)] = res;      // out[(b0+r)*512 + 4*tid]
    }
}

// ---------------------------------------------------------------------------
extern "C" void kernel_launch(void* const* d_in, const int* in_sizes, int n_in,
                              void* d_out, int out_size) {
    const float* input  = (const float*)d_in[0];
    const float* weight = (const float*)d_in[1];
    int s0 = in_sizes[0], s1 = in_sizes[1];
    if (s0 < s1) {  // weight is the smaller tensor (512*20); be robust to order
        const float* tmp = input; input = weight; weight = tmp;
        int ts = s0; s0 = s1; s1 = ts;
    }
    const int batch = s0 / KDIM;

    qr_kernel<<<1, MROWS>>>(weight);

    const int grid = (batch + BTILE - 1) / BTILE;
    gemm_kernel<<<grid, GTHREADS>>>(input, (float*)d_out, batch);
}

// round 2
// speedup vs baseline: 1.0375x; 1.0375x over previous
#include <cuda_runtime.h>

#define MROWS   512   // rows of weight / output dim
#define KDIM    20    // motion dim
#define OUT_DIM 512
#define BTILE   256   // batch rows per block in GEMM
#define GTHREADS 128  // 4 warps: 128 threads x 4 outputs = 512 outputs

// Q transposed: g_Qt[k*512 + o] = Q[o][k]
__device__ float g_Qt[KDIM * OUT_DIM];

// ---------------------------------------------------------------------------
// helpers
// ---------------------------------------------------------------------------
__device__ __forceinline__ float blockReduceSum(float x, float* red) {
    int lane = threadIdx.x & 31;
    int wid  = threadIdx.x >> 5;
    #pragma unroll
    for (int off = 16; off; off >>= 1) x += __shfl_xor_sync(0xffffffffu, x, off);
    if (lane == 0) red[wid] = x;
    __syncthreads();
    float s = (lane < 16) ? red[lane] : 0.f;   // 16 warps -> 16 partials
    #pragma unroll
    for (int off = 8; off; off >>= 1) s += __shfl_xor_sync(0xffffffffu, s, off);
    s = __shfl_sync(0xffffffffu, s, 0);
    __syncthreads();                            // protect red for next call
    return s;
}

__device__ __forceinline__ unsigned long long pack2(float lo, float hi) {
    unsigned long long r;
    asm("mov.b64 %0, {%1, %2};" : "=l"(r) : "f"(lo), "f"(hi));
    return r;
}

__device__ __forceinline__ unsigned long long ffma2(unsigned long long a,
                                                    unsigned long long b,
                                                    unsigned long long c) {
    unsigned long long d;
    asm("fma.rn.f32x2 %0, %1, %2, %3;" : "=l"(d) : "l"(a), "l"(b), "l"(c));
    return d;
}

__device__ __forceinline__ float hadd2(unsigned long long a) {
    float lo, hi;
    asm("mov.b64 {%0, %1}, %2;" : "=f"(lo), "=f"(hi) : "l"(a));
    return lo + hi;
}

// ---------------------------------------------------------------------------
// Householder QR (LAPACK sgeqr2 + sorg2r conventions) of W + 1e-8, W: [512,20]
// Single block, 512 threads (one per row). Writes Q^T to g_Qt.
// ---------------------------------------------------------------------------
__global__ void qr_kernel(const float* __restrict__ W) {
    __shared__ float sA[KDIM][MROWS];   // column-major: sA[c][t] = A[t][c]
    __shared__ float sV[MROWS];
    __shared__ float sTau[KDIM];
    __shared__ float sRed[16];

    const int t    = threadIdx.x;
    const int lane = t & 31;
    const int wid  = t >> 5;

    #pragma unroll
    for (int c = 0; c < KDIM; ++c)
        sA[c][t] = W[t * KDIM + c] + 1e-8f;
    __syncthreads();

    // ---- factorization (geqr2) ----
    for (int j = 0; j < KDIM; ++j) {
        float a  = sA[j][t];
        float sq = (t > j) ? a * a : 0.f;
        float xnorm2 = blockReduceSum(sq, sRed);
        float alpha  = sA[j][j];
        float beta   = -copysignf(sqrtf(alpha * alpha + xnorm2), alpha); // LAPACK sign
        float tau    = (beta - alpha) / beta;
        float inv    = 1.f / (alpha - beta);
        float v      = (t == j) ? 1.f : ((t > j) ? a * inv : 0.f);
        sV[t] = v;
        if (t == j)      { sTau[j] = tau; sA[j][j] = beta; }
        else if (t > j)  { sA[j][t] = v; }   // store reflector
        __syncthreads();

        // trailing update: one warp per column
        for (int c = j + 1 + wid; c < KDIM; c += 16) {
            float w = 0.f;
            #pragma unroll
            for (int i = lane; i < MROWS; i += 32) w += sV[i] * sA[c][i];
            #pragma unroll
            for (int off = 16; off; off >>= 1) w += __shfl_xor_sync(0xffffffffu, w, off);
            float tw = sTau[j] * w;
            #pragma unroll
            for (int i = lane; i < MROWS; i += 32) sA[c][i] -= tw * sV[i];
        }
        __syncthreads();
    }

    // ---- form Q in place (org2r) ----
    for (int j = KDIM - 1; j >= 0; --j) {
        float tau = sTau[j];
        float vt  = (t == j) ? 1.f : ((t > j) ? sA[j][t] : 0.f);
        sV[t] = vt;
        __syncthreads();

        for (int c = j + 1 + wid; c < KDIM; c += 16) {
            float w = 0.f;
            #pragma unroll
            for (int i = lane; i < MROWS; i += 32) w += sV[i] * sA[c][i];
            #pragma unroll
            for (int off = 16; off; off >>= 1) w += __shfl_xor_sync(0xffffffffu, w, off);
            float tw = tau * w;
            #pragma unroll
            for (int i = lane; i < MROWS; i += 32) sA[c][i] -= tw * sV[i];
        }
        __syncthreads();
        sA[j][t] = (t == j) ? (1.f - tau) : ((t > j) ? -tau * vt : 0.f);
        __syncthreads();
    }

    // store Q^T (coalesced per column)
    #pragma unroll
    for (int k = 0; k < KDIM; ++k)
        g_Qt[k * OUT_DIM + t] = sA[k][t];
}

// ---------------------------------------------------------------------------
// out[b][o] = sum_k input[b][k] * Q[o][k]
// Q register-resident, paired along k: q[c][p] = (Q[o][2p], Q[o][2p+1]).
// Input staged raw in smem (no duplication): row read = 5 LDS.128, each giving
// two (x_{2p}, x_{2p+1}) f32x2 operands. 40 FFMA2 + 4 horizontal adds per row.
// ---------------------------------------------------------------------------
__global__ void __launch_bounds__(GTHREADS, 4)
gemm_kernel(const float* __restrict__ input, float* __restrict__ out, int batch) {
    __shared__ float sIn[BTILE * KDIM];   // 20 KB

    const int tid = threadIdx.x;
    const long long b0 = (long long)blockIdx.x * BTILE;
    int rows = (batch - b0 < BTILE) ? (int)(batch - b0) : BTILE;

    // load this thread's Q columns (o = 4*tid .. 4*tid+3), paired along k
    unsigned long long q0[KDIM / 2], q1[KDIM / 2], q2[KDIM / 2], q3[KDIM / 2];
    #pragma unroll
    for (int p = 0; p < KDIM / 2; ++p) {
        float4 e = reinterpret_cast<const float4*>(g_Qt + (2 * p)     * OUT_DIM)[tid];
        float4 o = reinterpret_cast<const float4*>(g_Qt + (2 * p + 1) * OUT_DIM)[tid];
        q0[p] = pack2(e.x, o.x);
        q1[p] = pack2(e.y, o.y);
        q2[p] = pack2(e.z, o.z);
        q3[p] = pack2(e.w, o.w);
    }

    // stage input tile (raw copy, float4-vectorized)
    const float4* inBlk = reinterpret_cast<const float4*>(input + b0 * KDIM);
    float4* sIn4 = reinterpret_cast<float4*>(sIn);
    const int n4 = rows * KDIM / 4;            // rows*5 float4s
    for (int i = tid; i < n4; i += GTHREADS) {
        sIn4[i] = inBlk[i];
    }
    __syncthreads();

    float4* outp = reinterpret_cast<float4*>(out + b0 * OUT_DIM) + tid;

    #pragma unroll 2
    for (int r = 0; r < rows; ++r) {
        // row base: 20 floats = 80 bytes, 16B-aligned
        const ulonglong2* row = reinterpret_cast<const ulonglong2*>(sIn + r * KDIM);
        unsigned long long acc0 = 0ull, acc1 = 0ull, acc2 = 0ull, acc3 = 0ull;
        #pragma unroll
        for (int p = 0; p < KDIM / 4; ++p) {   // 5 LDS.128
            ulonglong2 x = row[p];             // x.x=(x_{4p},x_{4p+1}) x.y=(x_{4p+2},x_{4p+3})
            acc0 = ffma2(x.x, q0[2 * p],     acc0);
            acc1 = ffma2(x.x, q1[2 * p],     acc1);
            acc2 = ffma2(x.x, q2[2 * p],     acc2);
            acc3 = ffma2(x.x, q3[2 * p],     acc3);
            acc0 = ffma2(x.y, q0[2 * p + 1], acc0);
            acc1 = ffma2(x.y, q1[2 * p + 1], acc1);
            acc2 = ffma2(x.y, q2[2 * p + 1], acc2);
            acc3 = ffma2(x.y, q3[2 * p + 1], acc3);
        }
        float4 res;
        res.x = hadd2(acc0);
        res.y = hadd2(acc1);
        res.z = hadd2(acc2);
        res.w = hadd2(acc3);
        outp[(long long)r * (OUT_DIM / 4)] = res;      // out[(b0+r)*512 + 4*tid]
    }
}

// ---------------------------------------------------------------------------
extern "C" void kernel_launch(void* const* d_in, const int* in_sizes, int n_in,
                              void* d_out, int out_size) {
    const float* input  = (const float*)d_in[0];
    const float* weight = (const float*)d_in[1];
    int s0 = in_sizes[0], s1 = in_sizes[1];
    if (s0 < s1) {  // weight is the smaller tensor (512*20); be robust to order
        const float* tmp = input; input = weight; weight = tmp;
        int ts = s0; s0 = s1; s1 = ts;
    }
    const int batch = s0 / KDIM;

    qr_kernel<<<1, MROWS>>>(weight);

    const int grid = (batch + BTILE - 1) / BTILE;
    gemm_kernel<<<grid, GTHREADS>>>(input, (float*)d_out, batch);
}